// round 11
// baseline (speedup 1.0000x reference)
#include <cuda_runtime.h>
#include <cstdint>
#include <cstddef>

#define TAME_F  100000.0f
#define TAME2_F 1.0e10f
#define NTHR    32

__device__ __forceinline__ float frsq(float x) {
    float r;
    asm("rsqrt.approx.f32 %0, %1;" : "=f"(r) : "f"(x));
    return r;
}

// k=1, 128 blocks x 32 threads: 128 warps, one per SM. Each warp keeps a
// private SMSP (dispatch isolation, R7) AND a private per-SM L1tex/LSU.
// Rationale: R8/R10 showed the 75-cyc period is invariant to instruction
// count/schedule; the fixed binder matches per-SM store-wavefront throughput
// (4 warps x 3 STG x 3 lines x ~2.07 cyc = 75). With 1 warp/SM the store
// wavefront load (9 wf/step ~ 19 cyc) ducks under the dispatch/chain floor.
__global__ void __launch_bounds__(NTHR, 1)
tithte_kernel(const float* __restrict__ state0,
              const float* __restrict__ params,
              const float* __restrict__ ed,
              const int*   __restrict__ dtp,
              float*       __restrict__ out,
              int B, int T)
{
    extern __shared__ float4 sm4[];   // [0..T+1] rows {T_out, heat, solar, 0}

    const int tid = threadIdx.x;

    #pragma unroll 4
    for (int r = tid; r < T + 2; r += NTHR) {
        float4 v = make_float4(0.f, 0.f, 0.f, 0.f);
        if (r < T) { v.x = ed[3*r]; v.y = ed[3*r+1]; v.z = ed[3*r+2]; }
        sm4[r] = v;
    }
    __syncthreads();

    const int b = blockIdx.x * NTHR + tid;

    const float dtf = (float)dtp[0];
    const float C1 = params[b*6+0], R1 = params[b*6+1];
    const float C2 = params[b*6+2], R2 = params[b*6+3];
    const float C3 = params[b*6+4], R3 = params[b*6+5];

    const float a1 = dtf / C1, a2 = dtf / C2, a3 = dtf / C3;
    const float iR1 = 1.0f / R1, iR2 = 1.0f / R2, iR3 = 1.0f / R3;

    const float m12 = a1 * iR2, m13 = a1 * iR1, m11 = -(m12 + m13);
    const float m21 = a2 * iR2, m22 = -m21;
    const float m31 = a3 * iR1, k33 = a3 * iR3, m33 = -(m31 + k33);

    float s1 = state0[b*3+0], s2 = state0[b*3+1], s3 = state0[b*3+2];

    // ---- prologue: step-0 x, h, tx from row 0; issue r(0) interleaved ----
    float4 row0 = sm4[0];
    float c1 = a1  * row0.z;
    float c2 = a2  * row0.y;
    float c3 = k33 * row0.x;
    float u1 = fmaf(m12, s2, fmaf(m13, s3, c1));
    float u2 = fmaf(m22, s2, c2);
    float u3 = fmaf(m33, s3, c3);
    float x1 = fmaf(m11, s1, u1);
    float x2 = fmaf(m21, s1, u2);
    float x3 = fmaf(m31, s1, u3);
    float h3 = fmaf(x3, x3, TAME2_F);
    float r3 = frsq(h3);
    float tx3 = x3 * TAME_F;
    float h2 = fmaf(x2, x2, TAME2_F);
    float r2 = frsq(h2);
    float tx2 = x2 * TAME_F;
    float h1 = fmaf(x1, x1, TAME2_F);
    float r1 = frsq(h1);
    float tx1 = x1 * TAME_F;

    float4 nr = sm4[1];        // prefetched row 1

    float* op = out + (size_t)b * 3;
    const size_t grow = (size_t)B * 3;

    // ---- peeled t = 0 (no store of a previous row yet) ----
    {
        c1 = a1  * nr.z;
        c2 = a2  * nr.y;
        c3 = k33 * nr.x;
        nr = sm4[2];
        s3 = fmaf(tx3, r3, s3);
        s2 = fmaf(tx2, r2, s2);
        s1 = fmaf(tx1, r1, s1);
        u1 = fmaf(m12, s2, fmaf(m13, s3, c1));
        u2 = fmaf(m22, s2, c2);
        u3 = fmaf(m33, s3, c3);
        x1 = fmaf(m11, s1, u1);
        x2 = fmaf(m21, s1, u2);
        x3 = fmaf(m31, s1, u3);
        h3 = fmaf(x3, x3, TAME2_F);
        r3 = frsq(h3);
        tx3 = x3 * TAME_F;
        h2 = fmaf(x2, x2, TAME2_F);
        r2 = frsq(h2);
        tx2 = x2 * TAME_F;
        h1 = fmaf(x1, x1, TAME2_F);
        r1 = frsq(h1);
        tx1 = x1 * TAME_F;
    }

    // steady state: at iteration t, s holds s(t-1); store it in the MUFU
    // shadow, then consume r to advance.
    #pragma unroll 8
    for (int t = 1; t < T; ++t) {
        op[0] = s1; op[1] = s2; op[2] = s3;   // store s(t-1)
        op += grow;
        c1 = a1  * nr.z;                      // c(t+1)
        c2 = a2  * nr.y;
        c3 = k33 * nr.x;
        nr = sm4[t + 2];                      // prefetch (zero-padded)

        // consume r in arrival order (r3 issued first)
        s3 = fmaf(tx3, r3, s3);
        s2 = fmaf(tx2, r2, s2);
        s1 = fmaf(tx1, r1, s1);

        // u-trees from early s2,s3; one shallow fma on the late s1 per x
        u1 = fmaf(m12, s2, fmaf(m13, s3, c1));
        u2 = fmaf(m22, s2, c2);
        u3 = fmaf(m33, s3, c3);
        x1 = fmaf(m11, s1, u1);
        x2 = fmaf(m21, s1, u2);
        x3 = fmaf(m31, s1, u3);

        // h -> MUFU interleaved with the tx stream
        h3 = fmaf(x3, x3, TAME2_F);
        r3 = frsq(h3);
        tx3 = x3 * TAME_F;
        h2 = fmaf(x2, x2, TAME2_F);
        r2 = frsq(h2);
        tx2 = x2 * TAME_F;
        h1 = fmaf(x1, x1, TAME2_F);
        r1 = frsq(h1);
        tx1 = x1 * TAME_F;
    }

    op[0] = s1; op[1] = s2; op[2] = s3;       // row T-1
}

extern "C" void kernel_launch(void* const* d_in, const int* in_sizes, int n_in,
                              void* d_out, int out_size) {
    const float* state0 = (const float*)d_in[0];
    const float* params = (const float*)d_in[1];
    const float* ed     = (const float*)d_in[2];
    const int*   dtp    = (const int*)d_in[3];
    float* out = (float*)d_out;

    const int B = in_sizes[0] / 3;   // (B, 3)
    const int T = in_sizes[2] / 3;   // (T, 3)

    const int blocks = B / NTHR;     // 128 -> one warp per SM
    const size_t smem = (size_t)(T + 2) * sizeof(float4);

    cudaFuncSetAttribute(tithte_kernel,
                         cudaFuncAttributeMaxDynamicSharedMemorySize, (int)smem);
    tithte_kernel<<<blocks, NTHR, smem>>>(state0, params, ed, dtp, out, B, T);
}

// round 12
// speedup vs baseline: 1.1505x; 1.1505x over previous
#include <cuda_runtime.h>
#include <cstdint>
#include <cstddef>

#define TAME_F  100000.0f
#define TAME2_F 1.0e10f
#define NTHR    128
#define BFIX    4096
#define TFIX    8760
#define GROW3   (BFIX * 3)          // floats per time row

__device__ __forceinline__ float frsq(float x) {
    float r;
    asm("rsqrt.approx.f32 %0, %1;" : "=f"(r) : "f"(x));
    return r;
}

// k=1, 32 blocks x 128 threads: 128 warps on 128 distinct SMSPs (proven best:
// R7 co-residency and R11 1-warp/SM both regressed). Body = R10 (u-trees,
// interleaved MUFU, deferred store) + compile-time shapes: immediate STG
// offsets across an explicit 8x unrolled body, streaming (.cs) stores.
__global__ void __launch_bounds__(NTHR, 1)
tithte_kernel(const float* __restrict__ state0,
              const float* __restrict__ params,
              const float* __restrict__ ed,
              const int*   __restrict__ dtp,
              float*       __restrict__ out)
{
    extern __shared__ float4 sm4[];   // [0..TFIX+1] rows {T_out, heat, solar, 0}

    const int tid = threadIdx.x;

    #pragma unroll 4
    for (int r = tid; r < TFIX + 2; r += NTHR) {
        float4 v = make_float4(0.f, 0.f, 0.f, 0.f);
        if (r < TFIX) { v.x = ed[3*r]; v.y = ed[3*r+1]; v.z = ed[3*r+2]; }
        sm4[r] = v;
    }
    __syncthreads();

    const int b = blockIdx.x * NTHR + tid;

    const float dtf = (float)dtp[0];
    const float C1 = params[b*6+0], R1 = params[b*6+1];
    const float C2 = params[b*6+2], R2 = params[b*6+3];
    const float C3 = params[b*6+4], R3 = params[b*6+5];

    const float a1 = dtf / C1, a2 = dtf / C2, a3 = dtf / C3;
    const float iR1 = 1.0f / R1, iR2 = 1.0f / R2, iR3 = 1.0f / R3;

    const float m12 = a1 * iR2, m13 = a1 * iR1, m11 = -(m12 + m13);
    const float m21 = a2 * iR2, m22 = -m21;
    const float m31 = a3 * iR1, k33 = a3 * iR3, m33 = -(m31 + k33);

    float s1 = state0[b*3+0], s2 = state0[b*3+1], s3 = state0[b*3+2];

    // ---- prologue: step-0 x, h, tx from row 0; issue r(0) interleaved ----
    float4 row0 = sm4[0];
    float c1 = a1  * row0.z;
    float c2 = a2  * row0.y;
    float c3 = k33 * row0.x;
    float u1 = fmaf(m12, s2, fmaf(m13, s3, c1));
    float u2 = fmaf(m22, s2, c2);
    float u3 = fmaf(m33, s3, c3);
    float x1 = fmaf(m11, s1, u1);
    float x2 = fmaf(m21, s1, u2);
    float x3 = fmaf(m31, s1, u3);
    float h3 = fmaf(x3, x3, TAME2_F);
    float r3 = frsq(h3);
    float tx3 = x3 * TAME_F;
    float h2 = fmaf(x2, x2, TAME2_F);
    float r2 = frsq(h2);
    float tx2 = x2 * TAME_F;
    float h1 = fmaf(x1, x1, TAME2_F);
    float r1 = frsq(h1);
    float tx1 = x1 * TAME_F;

    float4 nr = sm4[1];        // prefetched row 1

    float* op = out + (size_t)b * 3;

    // ---- peeled t = 0 (no store of a previous row yet) ----
    {
        c1 = a1  * nr.z;
        c2 = a2  * nr.y;
        c3 = k33 * nr.x;
        nr = sm4[2];
        s3 = fmaf(tx3, r3, s3);
        s2 = fmaf(tx2, r2, s2);
        s1 = fmaf(tx1, r1, s1);
        u1 = fmaf(m12, s2, fmaf(m13, s3, c1));
        u2 = fmaf(m22, s2, c2);
        u3 = fmaf(m33, s3, c3);
        x1 = fmaf(m11, s1, u1);
        x2 = fmaf(m21, s1, u2);
        x3 = fmaf(m31, s1, u3);
        h3 = fmaf(x3, x3, TAME2_F);
        r3 = frsq(h3);
        tx3 = x3 * TAME_F;
        h2 = fmaf(x2, x2, TAME2_F);
        r2 = frsq(h2);
        tx2 = x2 * TAME_F;
        h1 = fmaf(x1, x1, TAME2_F);
        r1 = frsq(h1);
        tx1 = x1 * TAME_F;
    }

    // one simulation step; stores s(t-1) at immediate offset j*GROW3 from op,
    // in the shadow of the in-flight MUFUs issued by the previous step.
#define STEP(TIDX, J)                                                        \
    {                                                                        \
        __stcs(op + (J)*GROW3 + 0, s1);                                      \
        __stcs(op + (J)*GROW3 + 1, s2);                                      \
        __stcs(op + (J)*GROW3 + 2, s3);                                      \
        c1 = a1  * nr.z;                                                     \
        c2 = a2  * nr.y;                                                     \
        c3 = k33 * nr.x;                                                     \
        nr = sm4[(TIDX) + 2];                                                \
        s3 = fmaf(tx3, r3, s3);                                              \
        s2 = fmaf(tx2, r2, s2);                                              \
        s1 = fmaf(tx1, r1, s1);                                              \
        u1 = fmaf(m12, s2, fmaf(m13, s3, c1));                               \
        u2 = fmaf(m22, s2, c2);                                              \
        u3 = fmaf(m33, s3, c3);                                              \
        x1 = fmaf(m11, s1, u1);                                              \
        x2 = fmaf(m21, s1, u2);                                              \
        x3 = fmaf(m31, s1, u3);                                              \
        h3 = fmaf(x3, x3, TAME2_F);                                          \
        r3 = frsq(h3);                                                       \
        tx3 = x3 * TAME_F;                                                   \
        h2 = fmaf(x2, x2, TAME2_F);                                          \
        r2 = frsq(h2);                                                       \
        tx2 = x2 * TAME_F;                                                   \
        h1 = fmaf(x1, x1, TAME2_F);                                          \
        r1 = frsq(h1);                                                       \
        tx1 = x1 * TAME_F;                                                   \
    }

    // main loop: t = 1 .. 8752 in chunks of 8 (8752 = 8 * 1094)
    int t = 1;
    #pragma unroll 1
    for (int blk = 0; blk < (TFIX - 8) / 8; ++blk) {   // 1094 iterations
        STEP(t + 0, 0)
        STEP(t + 1, 1)
        STEP(t + 2, 2)
        STEP(t + 3, 3)
        STEP(t + 4, 4)
        STEP(t + 5, 5)
        STEP(t + 6, 6)
        STEP(t + 7, 7)
        op += 8 * GROW3;
        t += 8;
    }
    // tail: t = 8753 .. 8759 (7 steps)
    STEP(t + 0, 0)
    STEP(t + 1, 1)
    STEP(t + 2, 2)
    STEP(t + 3, 3)
    STEP(t + 4, 4)
    STEP(t + 5, 5)
    STEP(t + 6, 6)
    op += 7 * GROW3;

    // final row T-1
    __stcs(op + 0, s1);
    __stcs(op + 1, s2);
    __stcs(op + 2, s3);
#undef STEP
}

extern "C" void kernel_launch(void* const* d_in, const int* in_sizes, int n_in,
                              void* d_out, int out_size) {
    const float* state0 = (const float*)d_in[0];
    const float* params = (const float*)d_in[1];
    const float* ed     = (const float*)d_in[2];
    const int*   dtp    = (const int*)d_in[3];
    float* out = (float*)d_out;

    const int blocks = BFIX / NTHR;   // 32 -> 1 warp per SMSP chip-wide
    const size_t smem = (size_t)(TFIX + 2) * sizeof(float4);

    cudaFuncSetAttribute(tithte_kernel,
                         cudaFuncAttributeMaxDynamicSharedMemorySize, (int)smem);
    tithte_kernel<<<blocks, NTHR, smem>>>(state0, params, ed, dtp, out);
}